// round 14
// baseline (speedup 1.0000x reference)
#include <cuda_runtime.h>
#include <stdint.h>

// CubeSpherePadding2D, p=1: [16,64,6,96,96] f32 -> [16,64,6,98,98] f32.
// Pure gather of the original input (reference's 24 sequential edge writes
// resolved analytically; rel_err==0 verified rounds 1-13).
//
// Structure (rounds 11-12, kept): one CTA per slice; assemble the 98x98 tile
// in SMEM (aligned LDG.128 interior + scalar edge gather), then store the
// slice as 2401 aligned STG.128. Block 512 -> full residency (4 CTAs/SM).
//
// Round-13 change: phase-1a STS bank conflicts. The shifted scalar stores had
// lanes strided 4 floats -> systematic 4-way conflicts (dominant smem cost,
// L1 pipe 61%). Rotating each lane's write order by (lane>>3)&3 gives 32
// distinct banks per STS round -> conflict-free. Same addresses/values.

#define H 96
#define W 96
#define OH 98
#define OW 98
#define FACE (H * W)        // 9216
#define OFACE (OH * OW)     // 9604
#define NSLICES 6144        // 16*64*6
#define NT 512

__device__ __forceinline__ int src_off(int g, int y, int x) {
    return g * FACE + y * W + x;
}

// Source offset within the slice's 6-face block for a border output cell
// (f, r, c). Returns -1 for the zero corners (faces 0-3). Verified exact.
__device__ __forceinline__ int edge_src_offset(int f, int r, int c) {
    bool rin = (unsigned)(r - 1) < 96u;
    bool cin = (unsigned)(c - 1) < 96u;

    if (rin && cin) {
        return src_off(f, r - 1, c - 1);
    }
    if (cin) {                              // top/bottom row, non-corner
        bool top = (r == 0);
        switch (f) {
            case 0: return top ? src_off(4, 95, c - 1)   : src_off(5, 0, c - 1);
            case 1: return top ? src_off(4, 96 - c, 95)  : src_off(5, c - 1, 95);
            case 2: return top ? src_off(4, 0, 96 - c)   : src_off(5, 95, 96 - c);
            case 3: return top ? src_off(4, c - 1, 0)    : src_off(5, 96 - c, 0);
            case 4: return top ? src_off(2, 0, 96 - c)   : src_off(0, 0, c - 1);
            default:return top ? src_off(0, 95, c - 1)   : src_off(2, 95, 96 - c);
        }
    }
    if (rin) {                              // left/right column, non-corner
        bool right = (c == 97);
        switch (f) {
            case 0: return right ? src_off(1, r - 1, 0)  : src_off(3, r - 1, 95);
            case 1: return right ? src_off(2, r - 1, 0)  : src_off(0, r - 1, 95);
            case 2: return right ? src_off(3, r - 1, 0)  : src_off(1, r - 1, 95);
            case 3: return right ? src_off(0, r - 1, 0)  : src_off(2, r - 1, 95);
            case 4: return right ? src_off(1, 0, 96 - r) : src_off(3, 0, r - 1);
            default:return right ? src_off(1, 95, r - 1) : src_off(3, 95, 96 - r);
        }
    }
    // corners: faces 0-3 read still-zero padding (reference assignment order);
    // faces 4,5 resolve depth-2 to original data.
    if (f == 4) {
        if (r == 0) return (c == 0) ? src_off(3, 0, 0)   : src_off(1, 0, 95);
        else        return (c == 0) ? src_off(3, 0, 95)  : src_off(1, 0, 0);
    }
    if (f == 5) {
        if (r == 0) return (c == 0) ? src_off(3, 95, 95) : src_off(1, 95, 0);
        else        return (c == 0) ? src_off(3, 95, 0)  : src_off(1, 95, 95);
    }
    return -1;
}

__global__ void __launch_bounds__(NT)
cube_pad_smem_kernel(const float* __restrict__ in,
                     float* __restrict__ out) {
    __shared__ __align__(16) float tile[OFACE];   // 38,416 B

    const int s   = blockIdx.x;                   // slice 0..6143
    const int tid = threadIdx.x;
    const int f   = s % 6;
    const float* __restrict__ B0 = in + (size_t)(s - f) * FACE;

    // Phase 1a: interior — aligned LDG.128; rotated scalar STS (conflict-free).
    const float4* __restrict__ in4 =
        reinterpret_cast<const float4*>(in + (size_t)s * FACE);
    const int g = (tid >> 3) & 3;                 // per-lane write rotation
    #pragma unroll
    for (int i = tid; i < FACE / 4; i += NT) {    // 2304 -> 4.5 iters
        float4 v = __ldg(in4 + i);
        int row = i / (W / 4);
        int c4  = i - row * (W / 4);
        int b   = (row + 1) * OW + c4 * 4 + 1;
        #pragma unroll
        for (int k = 0; k < 4; ++k) {
            int e = (k + g) & 3;
            float val = (e == 0) ? v.x : (e == 1) ? v.y : (e == 2) ? v.z : v.w;
            tile[b + e] = val;
        }
    }

    // Phase 1b: 388 border cells (two full rows incl. corners + two columns).
    for (int e = tid; e < 388; e += NT) {
        int r, c;
        if (e < 98)       { r = 0;             c = e;      }
        else if (e < 196) { r = 97;            c = e - 98; }
        else if (e < 292) { r = 1 + (e - 196); c = 0;      }
        else              { r = 1 + (e - 292); c = 97;     }
        int off = edge_src_offset(f, r, c);
        tile[r * OW + c] = (off >= 0) ? __ldg(B0 + off) : 0.0f;
    }

    __syncthreads();

    // Phase 2: write the whole slice as aligned float4s (2401 per slice).
    float4* __restrict__ out4 =
        reinterpret_cast<float4*>(out) + (size_t)s * (OFACE / 4);
    const float4* __restrict__ t4 = reinterpret_cast<const float4*>(tile);
    #pragma unroll
    for (int i = tid; i < OFACE / 4; i += NT) {   // 2401 -> ~4.7 iters
        out4[i] = t4[i];
    }
}

extern "C" void kernel_launch(void* const* d_in, const int* in_sizes, int n_in,
                              void* d_out, int out_size) {
    const float* in = (const float*)d_in[0];
    float* out = (float*)d_out;

    cube_pad_smem_kernel<<<NSLICES, NT>>>(in, out);
}

// round 15
// speedup vs baseline: 1.3385x; 1.3385x over previous
#include <cuda_runtime.h>
#include <stdint.h>

// CubeSpherePadding2D, p=1: [16,64,6,96,96] f32 -> [16,64,6,98,98] f32.
// Pure gather of the original input (reference's 24 sequential edge writes
// resolved analytically; rel_err==0 verified rounds 1-14).
//
// Structure: one CTA per slice; assemble the 98x98 tile in SMEM (aligned
// LDG.128 interior + scalar edge gather), then store the slice to GMEM.
//
// Round-14: REVERT the rotated-STS experiment (it broke ptxas's front-batched
// LDG scheduling: MLP collapsed, 72->96us despite lower L1%). Phase 1a is
// byte-identical to the round-13 winner. Only phase 2 changes: the per-thread
// LDS.128+STG.128 copy loop is replaced by ONE cp.async.bulk (TMA 1D bulk
// store) of the whole 38,416B tile (16B aligned, 16-divisible), offloading
// the store stream to the TMA engine.

#define H 96
#define W 96
#define OH 98
#define OW 98
#define FACE (H * W)        // 9216
#define OFACE (OH * OW)     // 9604
#define NSLICES 6144        // 16*64*6
#define NT 512
#define TILE_BYTES (OFACE * 4)  // 38416

__device__ __forceinline__ int src_off(int g, int y, int x) {
    return g * FACE + y * W + x;
}

// Source offset within the slice's 6-face block for a border output cell
// (f, r, c). Returns -1 for the zero corners (faces 0-3). Verified exact.
__device__ __forceinline__ int edge_src_offset(int f, int r, int c) {
    bool rin = (unsigned)(r - 1) < 96u;
    bool cin = (unsigned)(c - 1) < 96u;

    if (rin && cin) {
        return src_off(f, r - 1, c - 1);
    }
    if (cin) {                              // top/bottom row, non-corner
        bool top = (r == 0);
        switch (f) {
            case 0: return top ? src_off(4, 95, c - 1)   : src_off(5, 0, c - 1);
            case 1: return top ? src_off(4, 96 - c, 95)  : src_off(5, c - 1, 95);
            case 2: return top ? src_off(4, 0, 96 - c)   : src_off(5, 95, 96 - c);
            case 3: return top ? src_off(4, c - 1, 0)    : src_off(5, 96 - c, 0);
            case 4: return top ? src_off(2, 0, 96 - c)   : src_off(0, 0, c - 1);
            default:return top ? src_off(0, 95, c - 1)   : src_off(2, 95, 96 - c);
        }
    }
    if (rin) {                              // left/right column, non-corner
        bool right = (c == 97);
        switch (f) {
            case 0: return right ? src_off(1, r - 1, 0)  : src_off(3, r - 1, 95);
            case 1: return right ? src_off(2, r - 1, 0)  : src_off(0, r - 1, 95);
            case 2: return right ? src_off(3, r - 1, 0)  : src_off(1, r - 1, 95);
            case 3: return right ? src_off(0, r - 1, 0)  : src_off(2, r - 1, 95);
            case 4: return right ? src_off(1, 0, 96 - r) : src_off(3, 0, r - 1);
            default:return right ? src_off(1, 95, r - 1) : src_off(3, 95, 96 - r);
        }
    }
    // corners: faces 0-3 read still-zero padding (reference assignment order);
    // faces 4,5 resolve depth-2 to original data.
    if (f == 4) {
        if (r == 0) return (c == 0) ? src_off(3, 0, 0)   : src_off(1, 0, 95);
        else        return (c == 0) ? src_off(3, 0, 95)  : src_off(1, 0, 0);
    }
    if (f == 5) {
        if (r == 0) return (c == 0) ? src_off(3, 95, 95) : src_off(1, 95, 0);
        else        return (c == 0) ? src_off(3, 95, 0)  : src_off(1, 95, 95);
    }
    return -1;
}

__global__ void __launch_bounds__(NT)
cube_pad_smem_kernel(const float* __restrict__ in,
                     float* __restrict__ out) {
    __shared__ __align__(16) float tile[OFACE];   // 38,416 B

    const int s   = blockIdx.x;                   // slice 0..6143
    const int tid = threadIdx.x;
    const int f   = s % 6;
    const float* __restrict__ B0 = in + (size_t)(s - f) * FACE;

    // Phase 1a: interior — 2304 aligned LDG.128, scalar STS shifted (+1,+1).
    // (Byte-identical to the round-13 winner: codegen keeps loads batched.)
    const float4* __restrict__ in4 =
        reinterpret_cast<const float4*>(in + (size_t)s * FACE);
    #pragma unroll
    for (int i = tid; i < FACE / 4; i += NT) {    // 2304 -> 4.5 iters
        float4 v = __ldg(in4 + i);
        int row = i / (W / 4);
        int c4  = i - row * (W / 4);
        int b   = (row + 1) * OW + c4 * 4 + 1;
        tile[b]     = v.x;
        tile[b + 1] = v.y;
        tile[b + 2] = v.z;
        tile[b + 3] = v.w;
    }

    // Phase 1b: 388 border cells (two full rows incl. corners + two columns).
    for (int e = tid; e < 388; e += NT) {
        int r, c;
        if (e < 98)       { r = 0;             c = e;      }
        else if (e < 196) { r = 97;            c = e - 98; }
        else if (e < 292) { r = 1 + (e - 196); c = 0;      }
        else              { r = 1 + (e - 292); c = 97;     }
        int off = edge_src_offset(f, r, c);
        tile[r * OW + c] = (off >= 0) ? __ldg(B0 + off) : 0.0f;
    }

    __syncthreads();

    // Phase 2: one TMA 1D bulk store of the whole tile (38,416 B).
    if (tid == 0) {
        // Make generic-proxy smem writes visible to the async proxy.
        asm volatile("fence.proxy.async.shared::cta;" ::: "memory");

        uint32_t saddr;
        asm("{ .reg .u64 t; cvta.to.shared.u64 t, %1; cvt.u32.u64 %0, t; }"
            : "=r"(saddr) : "l"((const void*)tile));
        const float* gdst = out + (size_t)s * OFACE;

        asm volatile(
            "cp.async.bulk.global.shared::cta.bulk_group [%0], [%1], %2;"
            :: "l"(gdst), "r"(saddr), "r"((int)TILE_BYTES)
            : "memory");
        asm volatile("cp.async.bulk.commit_group;" ::: "memory");
        asm volatile("cp.async.bulk.wait_group 0;" ::: "memory");
    }
}

extern "C" void kernel_launch(void* const* d_in, const int* in_sizes, int n_in,
                              void* d_out, int out_size) {
    const float* in = (const float*)d_in[0];
    float* out = (float*)d_out;

    cube_pad_smem_kernel<<<NSLICES, NT>>>(in, out);
}

// round 16
// speedup vs baseline: 1.3445x; 1.0045x over previous
#include <cuda_runtime.h>
#include <stdint.h>

// CubeSpherePadding2D, p=1: [16,64,6,96,96] f32 -> [16,64,6,98,98] f32.
// Pure gather of the original input (reference's 24 sequential edge writes
// resolved analytically; rel_err==0 verified rounds 1-15).
//
// Structure (round-15 winner, kept): one CTA per slice; assemble the 98x98
// tile in SMEM (aligned LDG.128 interior + scalar edge gather), then ONE
// cp.async.bulk (TMA 1D bulk store) of the 38,416B tile.
//
// Round-16 change: NT 512 -> 384. With 38.4KB smem the CTA/SM cap is 5; at
// 384 threads that's 5x384 = 1920/2048 threads (94%) vs 4x512 with one slot
// perpetually stuck in the TMA wait_group tail (measured occ 78.5%). The
// spare CTA slot hides the store-drain tail.

#define H 96
#define W 96
#define OH 98
#define OW 98
#define FACE (H * W)        // 9216
#define OFACE (OH * OW)     // 9604
#define NSLICES 6144        // 16*64*6
#define NT 384
#define TILE_BYTES (OFACE * 4)  // 38416

__device__ __forceinline__ int src_off(int g, int y, int x) {
    return g * FACE + y * W + x;
}

// Source offset within the slice's 6-face block for a border output cell
// (f, r, c). Returns -1 for the zero corners (faces 0-3). Verified exact.
__device__ __forceinline__ int edge_src_offset(int f, int r, int c) {
    bool rin = (unsigned)(r - 1) < 96u;
    bool cin = (unsigned)(c - 1) < 96u;

    if (rin && cin) {
        return src_off(f, r - 1, c - 1);
    }
    if (cin) {                              // top/bottom row, non-corner
        bool top = (r == 0);
        switch (f) {
            case 0: return top ? src_off(4, 95, c - 1)   : src_off(5, 0, c - 1);
            case 1: return top ? src_off(4, 96 - c, 95)  : src_off(5, c - 1, 95);
            case 2: return top ? src_off(4, 0, 96 - c)   : src_off(5, 95, 96 - c);
            case 3: return top ? src_off(4, c - 1, 0)    : src_off(5, 96 - c, 0);
            case 4: return top ? src_off(2, 0, 96 - c)   : src_off(0, 0, c - 1);
            default:return top ? src_off(0, 95, c - 1)   : src_off(2, 95, 96 - c);
        }
    }
    if (rin) {                              // left/right column, non-corner
        bool right = (c == 97);
        switch (f) {
            case 0: return right ? src_off(1, r - 1, 0)  : src_off(3, r - 1, 95);
            case 1: return right ? src_off(2, r - 1, 0)  : src_off(0, r - 1, 95);
            case 2: return right ? src_off(3, r - 1, 0)  : src_off(1, r - 1, 95);
            case 3: return right ? src_off(0, r - 1, 0)  : src_off(2, r - 1, 95);
            case 4: return right ? src_off(1, 0, 96 - r) : src_off(3, 0, r - 1);
            default:return right ? src_off(1, 95, r - 1) : src_off(3, 95, 96 - r);
        }
    }
    // corners: faces 0-3 read still-zero padding (reference assignment order);
    // faces 4,5 resolve depth-2 to original data.
    if (f == 4) {
        if (r == 0) return (c == 0) ? src_off(3, 0, 0)   : src_off(1, 0, 95);
        else        return (c == 0) ? src_off(3, 0, 95)  : src_off(1, 0, 0);
    }
    if (f == 5) {
        if (r == 0) return (c == 0) ? src_off(3, 95, 95) : src_off(1, 95, 0);
        else        return (c == 0) ? src_off(3, 95, 0)  : src_off(1, 95, 95);
    }
    return -1;
}

__global__ void __launch_bounds__(NT)
cube_pad_smem_kernel(const float* __restrict__ in,
                     float* __restrict__ out) {
    __shared__ __align__(16) float tile[OFACE];   // 38,416 B

    const int s   = blockIdx.x;                   // slice 0..6143
    const int tid = threadIdx.x;
    const int f   = s % 6;
    const float* __restrict__ B0 = in + (size_t)(s - f) * FACE;

    // Phase 1a: interior — 2304 aligned LDG.128, scalar STS shifted (+1,+1).
    const float4* __restrict__ in4 =
        reinterpret_cast<const float4*>(in + (size_t)s * FACE);
    #pragma unroll
    for (int i = tid; i < FACE / 4; i += NT) {    // 2304 -> 6 iters
        float4 v = __ldg(in4 + i);
        int row = i / (W / 4);
        int c4  = i - row * (W / 4);
        int b   = (row + 1) * OW + c4 * 4 + 1;
        tile[b]     = v.x;
        tile[b + 1] = v.y;
        tile[b + 2] = v.z;
        tile[b + 3] = v.w;
    }

    // Phase 1b: 388 border cells (two full rows incl. corners + two columns).
    for (int e = tid; e < 388; e += NT) {
        int r, c;
        if (e < 98)       { r = 0;             c = e;      }
        else if (e < 196) { r = 97;            c = e - 98; }
        else if (e < 292) { r = 1 + (e - 196); c = 0;      }
        else              { r = 1 + (e - 292); c = 97;     }
        int off = edge_src_offset(f, r, c);
        tile[r * OW + c] = (off >= 0) ? __ldg(B0 + off) : 0.0f;
    }

    __syncthreads();

    // Phase 2: one TMA 1D bulk store of the whole tile (38,416 B).
    if (tid == 0) {
        // Make generic-proxy smem writes visible to the async proxy.
        asm volatile("fence.proxy.async.shared::cta;" ::: "memory");

        uint32_t saddr;
        asm("{ .reg .u64 t; cvta.to.shared.u64 t, %1; cvt.u32.u64 %0, t; }"
            : "=r"(saddr) : "l"((const void*)tile));
        const float* gdst = out + (size_t)s * OFACE;

        asm volatile(
            "cp.async.bulk.global.shared::cta.bulk_group [%0], [%1], %2;"
            :: "l"(gdst), "r"(saddr), "r"((int)TILE_BYTES)
            : "memory");
        asm volatile("cp.async.bulk.commit_group;" ::: "memory");
        asm volatile("cp.async.bulk.wait_group 0;" ::: "memory");
    }
}

extern "C" void kernel_launch(void* const* d_in, const int* in_sizes, int n_in,
                              void* d_out, int out_size) {
    const float* in = (const float*)d_in[0];
    float* out = (float*)d_out;

    cube_pad_smem_kernel<<<NSLICES, NT>>>(in, out);
}